// round 12
// baseline (speedup 1.0000x reference)
#include <cuda_runtime.h>
#include <cuda_fp16.h>
#include <math_constants.h>
#include <stdint.h>

// SupCon multi-class loss, symmetric-half fused fp16 HMMA + online softmax.
// z: (8192, 128) fp32, labels: (8192,) int32 -> scalar fp32 loss.
// Block-pairs (I<=J): each 128x128 sim block folded row-wise (anchors I)
// and col-wise (anchors J). 512 thr/CTA, warp tile 32x32 -> 32 acc regs.

#define TAU_F 0.1f
#define LOG2E_F 1.4426950408889634f
#define LN2_F 0.69314718055994531f
#define SCALE_F (LOG2E_F / TAU_F)

#define BSZ 8192
#define DDIM 128
#define BLK 128
#define NB (BSZ / BLK)            // 64
#define NPAIR (NB * (NB + 1) / 2) // 2080
#define NTHR 512

// SMEM in halves; row stride 136 halves (272B) -> conflict-free ldmatrix.
#define RSTR 136
#define A_OFF 0
#define B_OFF (BLK * RSTR)
#define TILES_HALVES (2 * BLK * RSTR)          // 34816 halves = 69632 B
#define RED_ROW_OFF TILES_HALVES               // float4[128][4] = 8KB
#define RED_COL_OFF (TILES_HALVES + 4096)      // float4[128][4] = 8KB
#define SMEM_BYTES (TILES_HALVES * 2 + 16384)  // 86016

__device__ __half  g_zhi[BSZ * DDIM];
__device__ float4  g_part2[NB][BSZ];      // [otherBlock][row] partials, 8MB
__device__ double  g_sum;
__device__ int     g_cnt;

// ---------------- asm helpers ----------------
__device__ __forceinline__ float ex2(float x) {
    float y; asm("ex2.approx.ftz.f32 %0, %1;" : "=f"(y) : "f"(x)); return y;
}
__device__ __forceinline__ void cpa16(uint32_t sa, const void* g) {
    asm volatile("cp.async.cg.shared.global [%0], [%1], 16;" :: "r"(sa), "l"(g));
}
__device__ __forceinline__ void ldsm_x4(uint32_t* r, uint32_t addr) {
    asm volatile("ldmatrix.sync.aligned.m8n8.x4.shared.b16 {%0,%1,%2,%3}, [%4];"
                 : "=r"(r[0]), "=r"(r[1]), "=r"(r[2]), "=r"(r[3]) : "r"(addr));
}
__device__ __forceinline__ void mma16816(float* c, const uint32_t* a,
                                         uint32_t b0, uint32_t b1) {
    asm volatile(
        "mma.sync.aligned.m16n8k16.row.col.f32.f16.f16.f32 "
        "{%0,%1,%2,%3}, {%4,%5,%6,%7}, {%8,%9}, {%0,%1,%2,%3};"
        : "+f"(c[0]), "+f"(c[1]), "+f"(c[2]), "+f"(c[3])
        : "r"(a[0]), "r"(a[1]), "r"(a[2]), "r"(a[3]), "r"(b0), "r"(b1));
}

// ---------------- kernels ----------------
__global__ void supcon_convert_kernel(const float* __restrict__ z) {
    int i = blockIdx.x * blockDim.x + threadIdx.x;   // BSZ*DDIM/2 threads
    if (i == 0) { g_sum = 0.0; g_cnt = 0; }
    float2 f = reinterpret_cast<const float2*>(z)[i];
    reinterpret_cast<__half2*>(g_zhi)[i] = __floats2half2_rn(f.x, f.y);
}

__global__ __launch_bounds__(NTHR, 1)
void supcon_main_kernel(const int* __restrict__ labels) {
    extern __shared__ __half sh[];
    const int tid  = threadIdx.x;
    const int lane = tid & 31;
    const int w    = tid >> 5;
    const int wm   = w & 3;          // 4 warps over M (32 rows each)
    const int wn   = w >> 2;         // 4 warps over N (32 cols each)
    const uint32_t sbase = (uint32_t)__cvta_generic_to_shared(sh);

    // decode linear pair index -> (I, J), I <= J
    int k = blockIdx.x, I = 0;
    while (k >= NB - I) { k -= NB - I; ++I; }
    const int J = I + k;
    const bool diag = (I == J);
    const int rowBase = I * BLK, colBase = J * BLK;

    const uint4* zhi4 = reinterpret_cast<const uint4*>(g_zhi);

    // ---- load A (and B unless diag): 128 rows x 16 uint4 each ----
    #pragma unroll
    for (int it = 0; it < 4; ++it) {
        int idx = tid + it * NTHR; int row = idx >> 4, ch = idx & 15;
        cpa16(sbase + (A_OFF + row * RSTR + ch * 8) * 2,
              zhi4 + (rowBase + row) * 16 + ch);
    }
    if (!diag) {
        #pragma unroll
        for (int it = 0; it < 4; ++it) {
            int idx = tid + it * NTHR; int row = idx >> 4, ch = idx & 15;
            cpa16(sbase + (B_OFF + row * RSTR + ch * 8) * 2,
                  zhi4 + (colBase + row) * 16 + ch);
        }
    }
    asm volatile("cp.async.commit_group;" ::: "memory");
    asm volatile("cp.async.wait_group 0;" ::: "memory");
    __syncthreads();

    // ---- fragment addresses ----
    const int bB = diag ? A_OFF : B_OFF;
    const int arow = lane & 15, akad = (lane >> 4) * 8;
    uint32_t aAddr[2];
    #pragma unroll
    for (int mt = 0; mt < 2; ++mt)
        aAddr[mt] = sbase + (A_OFF + (wm * 32 + mt * 16 + arow) * RSTR + akad) * 2;
    const int brow = ((lane >> 4) << 3) + (lane & 7);
    const int bkad = ((lane >> 3) & 1) * 8;
    uint32_t bAddr[2];
    #pragma unroll
    for (int bt = 0; bt < 2; ++bt)
        bAddr[bt] = sbase + (bB + (wn * 32 + bt * 16 + brow) * RSTR + bkad) * 2;

    // ---- GEMM: warp tile 32x32, acc 32/thread ----
    float acc[2][4][4];
    #pragma unroll
    for (int mt = 0; mt < 2; ++mt)
        #pragma unroll
        for (int nt = 0; nt < 4; ++nt)
            #pragma unroll
            for (int e = 0; e < 4; ++e) acc[mt][nt][e] = 0.f;

    #pragma unroll
    for (int kc = 0; kc < 8; ++kc) {
        uint32_t ah[2][4], bh[2][4];
        #pragma unroll
        for (int mt = 0; mt < 2; ++mt) ldsm_x4(ah[mt], aAddr[mt] + kc * 32);
        #pragma unroll
        for (int bt = 0; bt < 2; ++bt) ldsm_x4(bh[bt], bAddr[bt] + kc * 32);
        #pragma unroll
        for (int mt = 0; mt < 2; ++mt)
            #pragma unroll
            for (int bt = 0; bt < 2; ++bt) {
                mma16816(acc[mt][bt * 2],     ah[mt], bh[bt][0], bh[bt][1]);
                mma16816(acc[mt][bt * 2 + 1], ah[mt], bh[bt][2], bh[bt][3]);
            }
    }
    // NOTE: no __syncthreads here — folds touch only registers + separate
    // smem region, so fold (FMA/MUFU) overlaps other warps' HMMA issue.

    // thread row r in [0,4): local row = wm*32 + (r>>1)*16 + ((r&1)<<3) + (lane>>2)
    // thread col j in [0,8): local col = wn*32 + (j>>1)*8 + (lane&3)*2 + (j&1)
    // acc element (r, j): acc[r>>1][j>>1][((r&1)<<1) | (j&1)]
    int li[4], lc[8];
    #pragma unroll
    for (int r = 0; r < 4; ++r)
        li[r] = __ldg(labels + rowBase + wm * 32 + (r >> 1) * 16 + ((r & 1) << 3) + (lane >> 2));
    #pragma unroll
    for (int j = 0; j < 8; ++j)
        lc[j] = __ldg(labels + colBase + wn * 32 + (j >> 1) * 8 + (lane & 3) * 2 + (j & 1));

    float4* red_row = reinterpret_cast<float4*>(sh + RED_ROW_OFF);  // [128][4]
    float4* red_col = reinterpret_cast<float4*>(sh + RED_COL_OFF);  // [128][4]

    // ---- row fold: 4 rows/thread, 8 cols each ----
    {
        float rm[4], rs[4], rps[4]; int rpc[4];
        #pragma unroll
        for (int r = 0; r < 4; ++r) {
            const int growr = rowBase + wm * 32 + (r >> 1) * 16 + ((r & 1) << 3) + (lane >> 2);
            float lh[8], tmax = -CUDART_INF_F, tps = 0.f; int tpc = 0;
            #pragma unroll
            for (int j = 0; j < 8; ++j) {
                float v = acc[r >> 1][j >> 1][((r & 1) << 1) | (j & 1)];
                int gcol = colBase + wn * 32 + (j >> 1) * 8 + (lane & 3) * 2 + (j & 1);
                bool dg = (gcol == growr);                  // only in diag blocks
                if (!dg && lc[j] == li[r]) { tps += v; tpc += 1; }
                float l = dg ? -CUDART_INF_F : v * SCALE_F;
                lh[j] = l;
                tmax = fmaxf(tmax, l);
            }
            float ss = 0.f;
            #pragma unroll
            for (int j = 0; j < 8; ++j) ss += ex2(lh[j] - tmax);
            rm[r] = tmax; rs[r] = ss; rps[r] = tps; rpc[r] = tpc;
        }
        #pragma unroll
        for (int r = 0; r < 4; ++r) {
            #pragma unroll
            for (int ox = 1; ox <= 2; ox <<= 1) {
                float mo  = __shfl_xor_sync(0xFFFFFFFFu, rm[r],  ox);
                float so  = __shfl_xor_sync(0xFFFFFFFFu, rs[r],  ox);
                float pso = __shfl_xor_sync(0xFFFFFFFFu, rps[r], ox);
                int   pco = __shfl_xor_sync(0xFFFFFFFFu, rpc[r], ox);
                float nm = fmaxf(rm[r], mo);
                rs[r] = rs[r] * ex2(rm[r] - nm) + so * ex2(mo - nm);
                rm[r] = nm; rps[r] += pso; rpc[r] += pco;
            }
        }
        if ((lane & 3) == 0) {
            #pragma unroll
            for (int r = 0; r < 4; ++r) {
                const int lrow = wm * 32 + (r >> 1) * 16 + ((r & 1) << 3) + (lane >> 2);
                red_row[lrow * 4 + wn] =
                    make_float4(rm[r], rs[r], rps[r], __int_as_float(rpc[r]));
            }
        }
    }

    // ---- col fold (symmetric contribution), skip for diagonal blocks ----
    if (!diag) {
        #pragma unroll
        for (int p = 0; p < 2; ++p) {       // 2 passes of 4 cols (reg pressure)
            float cm[4], cs[4], cps[4]; int cpc[4];
            #pragma unroll
            for (int jj = 0; jj < 4; ++jj) {
                const int j = p * 4 + jj;
                float lh[4], tmax = -CUDART_INF_F, tps = 0.f; int tpc = 0;
                #pragma unroll
                for (int r = 0; r < 4; ++r) {
                    float v = acc[r >> 1][j >> 1][((r & 1) << 1) | (j & 1)];
                    if (lc[j] == li[r]) { tps += v; tpc += 1; }   // no diag here
                    float l = v * SCALE_F;
                    lh[r] = l;
                    tmax = fmaxf(tmax, l);
                }
                float ss = 0.f;
                #pragma unroll
                for (int r = 0; r < 4; ++r) ss += ex2(lh[r] - tmax);
                cm[jj] = tmax; cs[jj] = ss; cps[jj] = tps; cpc[jj] = tpc;
            }
            // merge across the 8 threads (lane>>2) sharing each col
            #pragma unroll
            for (int jj = 0; jj < 4; ++jj) {
                #pragma unroll
                for (int ox = 4; ox <= 16; ox <<= 1) {
                    float mo  = __shfl_xor_sync(0xFFFFFFFFu, cm[jj],  ox);
                    float so  = __shfl_xor_sync(0xFFFFFFFFu, cs[jj],  ox);
                    float pso = __shfl_xor_sync(0xFFFFFFFFu, cps[jj], ox);
                    int   pco = __shfl_xor_sync(0xFFFFFFFFu, cpc[jj], ox);
                    float nm = fmaxf(cm[jj], mo);
                    cs[jj] = cs[jj] * ex2(cm[jj] - nm) + so * ex2(mo - nm);
                    cm[jj] = nm; cps[jj] += pso; cpc[jj] += pco;
                }
            }
            if (lane < 4) {
                #pragma unroll
                for (int jj = 0; jj < 4; ++jj) {
                    const int j = p * 4 + jj;
                    const int lcol = wn * 32 + (j >> 1) * 8 + (lane & 3) * 2 + (j & 1);
                    red_col[lcol * 4 + wm] =
                        make_float4(cm[jj], cs[jj], cps[jj], __int_as_float(cpc[jj]));
                }
            }
        }
    }
    __syncthreads();

    // ---- final per-row partial writes to gmem ----
    if (tid < BLK) {
        float4 p0 = red_row[tid * 4 + 0], p1 = red_row[tid * 4 + 1];
        float4 p2 = red_row[tid * 4 + 2], p3 = red_row[tid * 4 + 3];
        float M = fmaxf(fmaxf(p0.x, p1.x), fmaxf(p2.x, p3.x));
        float S = p0.y * ex2(p0.x - M) + p1.y * ex2(p1.x - M) +
                  p2.y * ex2(p2.x - M) + p3.y * ex2(p3.x - M);
        float PS = p0.z + p1.z + p2.z + p3.z;
        int PC = __float_as_int(p0.w) + __float_as_int(p1.w) +
                 __float_as_int(p2.w) + __float_as_int(p3.w);
        g_part2[J][rowBase + tid] = make_float4(M, S, PS, __int_as_float(PC));
    } else if (tid < 2 * BLK && !diag) {
        const int c = tid - BLK;
        float4 p0 = red_col[c * 4 + 0], p1 = red_col[c * 4 + 1];
        float4 p2 = red_col[c * 4 + 2], p3 = red_col[c * 4 + 3];
        float M = fmaxf(fmaxf(p0.x, p1.x), fmaxf(p2.x, p3.x));
        float S = p0.y * ex2(p0.x - M) + p1.y * ex2(p1.x - M) +
                  p2.y * ex2(p2.x - M) + p3.y * ex2(p3.x - M);
        float PS = p0.z + p1.z + p2.z + p3.z;
        int PC = __float_as_int(p0.w) + __float_as_int(p1.w) +
                 __float_as_int(p2.w) + __float_as_int(p3.w);
        g_part2[I][colBase + c] = make_float4(M, S, PS, __int_as_float(PC));
    }
}

__global__ void supcon_merge_kernel() {
    int i = blockIdx.x * blockDim.x + threadIdx.x;   // BSZ threads
    float M = -CUDART_INF_F, S = 0.f, PS = 0.f; int PC = 0;
    #pragma unroll 4
    for (int p = 0; p < NB; ++p) {
        float4 v = g_part2[p][i];
        float nm = fmaxf(M, v.x);
        S = S * ex2(M - nm) + v.y * ex2(v.x - nm);
        M = nm; PS += v.z; PC += __float_as_int(v.w);
    }
    double loss = 0.0; int valid = 0;
    if (PC > 0) {
        float lse = LN2_F * (M + log2f(S));   // natural-log lse
        loss = (double)(lse - PS / (TAU_F * (float)PC));
        valid = 1;
    }
    #pragma unroll
    for (int o = 16; o; o >>= 1) {
        loss  += __shfl_down_sync(0xFFFFFFFFu, loss, o);
        valid += __shfl_down_sync(0xFFFFFFFFu, valid, o);
    }
    if ((threadIdx.x & 31) == 0) {
        atomicAdd(&g_sum, loss);
        atomicAdd(&g_cnt, valid);
    }
}

__global__ void supcon_final_kernel(float* __restrict__ out) {
    int c = g_cnt; if (c < 1) c = 1;
    out[0] = (float)(g_sum / (double)c);
}

extern "C" void kernel_launch(void* const* d_in, const int* in_sizes, int n_in,
                              void* d_out, int out_size) {
    const float* z      = (const float*)d_in[0];
    const int*   labels = (const int*)d_in[1];
    float*       out    = (float*)d_out;

    static bool attr_set = false;
    if (!attr_set) {
        cudaFuncSetAttribute(supcon_main_kernel,
                             cudaFuncAttributeMaxDynamicSharedMemorySize,
                             SMEM_BYTES);
        attr_set = true;
    }

    supcon_convert_kernel<<<(BSZ * DDIM / 2) / 256, 256>>>(z);
    supcon_main_kernel<<<NPAIR, NTHR, SMEM_BYTES>>>(labels);
    supcon_merge_kernel<<<BSZ / 256, 256>>>();
    supcon_final_kernel<<<1, 1>>>(out);
}

// round 13
// speedup vs baseline: 1.1759x; 1.1759x over previous
#include <cuda_runtime.h>
#include <cuda_fp16.h>
#include <math_constants.h>
#include <stdint.h>

// SupCon multi-class loss: symmetric-half streamed fp16 HMMA + online softmax.
// z: (8192, 128) fp32, labels: (8192,) int32 -> scalar fp32 loss.
// Runs = (row-block I, chunk of <=8 col tiles J>=I). A_I persistent, B streamed
// (R9 pipeline). Row-fold accumulates across run; col-fold per tile gives the
// symmetric contribution. 512 thr, warp tile 32x32 (32 acc regs, no spill).

#define TAU_F 0.1f
#define LOG2E_F 1.4426950408889634f
#define LN2_F 0.69314718055994531f
#define SCALE_F (LOG2E_F / TAU_F)

#define BSZ 8192
#define DDIM 128
#define BLK 128
#define NB (BSZ / BLK)            // 64
#define NRUNS 288                 // sum_I ceil((64-I)/8)
#define CHUNK 8
#define NTHR 512

// SMEM in halves; row stride 136 halves (272B) -> conflict-free ldmatrix.
#define RSTR 136
#define A_OFF 0
#define B_OFFH(st) ((BLK * RSTR) + ((st) * (BLK * RSTR)))
#define TILES_BYTES (3 * BLK * RSTR * 2)       // 104448
#define RED_ROW_OFF TILES_BYTES                // float4[128][4] = 8KB
#define RED_COL_OFF (TILES_BYTES + 8192)       // float4[128][4] = 8KB
#define SMEM_BYTES (TILES_BYTES + 16384)       // 120832

__device__ __half  g_zhi[BSZ * DDIM];
__device__ float4  g_partC[NB][BSZ];      // col-fold partials: [I][global col]
__device__ float4  g_partR[CHUNK][BSZ];   // row-fold partials: [chunk][global row]
__device__ double  g_sum;
__device__ int     g_cnt;

// ---------------- asm helpers ----------------
__device__ __forceinline__ float ex2(float x) {
    float y; asm("ex2.approx.ftz.f32 %0, %1;" : "=f"(y) : "f"(x)); return y;
}
__device__ __forceinline__ void cpa16(uint32_t sa, const void* g) {
    asm volatile("cp.async.cg.shared.global [%0], [%1], 16;" :: "r"(sa), "l"(g));
}
__device__ __forceinline__ void ldsm_x4(uint32_t* r, uint32_t addr) {
    asm volatile("ldmatrix.sync.aligned.m8n8.x4.shared.b16 {%0,%1,%2,%3}, [%4];"
                 : "=r"(r[0]), "=r"(r[1]), "=r"(r[2]), "=r"(r[3]) : "r"(addr));
}
__device__ __forceinline__ void mma16816(float* c, const uint32_t* a,
                                         uint32_t b0, uint32_t b1) {
    asm volatile(
        "mma.sync.aligned.m16n8k16.row.col.f32.f16.f16.f32 "
        "{%0,%1,%2,%3}, {%4,%5,%6,%7}, {%8,%9}, {%0,%1,%2,%3};"
        : "+f"(c[0]), "+f"(c[1]), "+f"(c[2]), "+f"(c[3])
        : "r"(a[0]), "r"(a[1]), "r"(a[2]), "r"(a[3]), "r"(b0), "r"(b1));
}

// ---------------- kernels ----------------
__global__ void supcon_convert_kernel(const float* __restrict__ z) {
    int i = blockIdx.x * blockDim.x + threadIdx.x;   // BSZ*DDIM/2 threads
    if (i == 0) { g_sum = 0.0; g_cnt = 0; }
    float2 f = reinterpret_cast<const float2*>(z)[i];
    reinterpret_cast<__half2*>(g_zhi)[i] = __floats2half2_rn(f.x, f.y);
}

__global__ __launch_bounds__(NTHR, 1)
void supcon_main_kernel(const int* __restrict__ labels) {
    extern __shared__ __half sh[];
    const int tid  = threadIdx.x;
    const int lane = tid & 31;
    const int w    = tid >> 5;
    const int wm   = w & 3;          // 4 warps over M (32 rows each)
    const int wn   = w >> 2;         // 4 warps over N (32 cols each)
    const uint32_t sbase = (uint32_t)__cvta_generic_to_shared(sh);

    // decode run -> (I, c)
    int k = blockIdx.x, I = 0;
    for (;;) { int nc = (NB - I + CHUNK - 1) >> 3; if (k < nc) break; k -= nc; ++I; }
    const int c = k;
    const int J0 = I + c * CHUNK;
    const int nt = min(CHUNK, NB - J0);
    const int rowBase = I * BLK;

    const uint4* zhi4 = reinterpret_cast<const uint4*>(g_zhi);

    auto issue_b = [&](int J, int st) {
        #pragma unroll
        for (int it = 0; it < 4; ++it) {
            int idx = tid + it * NTHR;      // 0..2047
            int row = idx >> 4, ch = idx & 15;
            cpa16(sbase + (B_OFFH(st) + row * RSTR + ch * 8) * 2,
                  zhi4 + (J * BLK + row) * 16 + ch);
        }
        asm volatile("cp.async.commit_group;" ::: "memory");
    };

    // ---- prologue: A_I + B(J0) in one group ----
    #pragma unroll
    for (int it = 0; it < 4; ++it) {
        int idx = tid + it * NTHR;
        int row = idx >> 4, ch = idx & 15;
        cpa16(sbase + (A_OFF + row * RSTR + ch * 8) * 2,
              zhi4 + (rowBase + row) * 16 + ch);
    }
    issue_b(J0, 0);
    asm volatile("cp.async.wait_group 0;" ::: "memory");
    __syncthreads();

    // ---- fragment addresses ----
    const int arow = lane & 15, akad = (lane >> 4) * 8;
    uint32_t aAddr[2];
    #pragma unroll
    for (int mt = 0; mt < 2; ++mt)
        aAddr[mt] = sbase + (A_OFF + (wm * 32 + mt * 16 + arow) * RSTR + akad) * 2;
    const int brow = ((lane >> 4) << 3) + (lane & 7);
    const int bkad = ((lane >> 3) & 1) * 8;
    uint32_t bAddr[2][2];
    #pragma unroll
    for (int st = 0; st < 2; ++st)
        #pragma unroll
        for (int bt = 0; bt < 2; ++bt)
            bAddr[st][bt] = sbase + (B_OFFH(st) +
                            (wn * 32 + bt * 16 + brow) * RSTR + bkad) * 2;

    // thread row r in [0,4): local row = wm*32 + (r>>1)*16 + ((r&1)<<3) + (lane>>2)
    // thread col j in [0,8): local col = wn*32 + (j>>1)*8 + (lane&3)*2 + (j&1)
    int li[4];
    #pragma unroll
    for (int r = 0; r < 4; ++r)
        li[r] = __ldg(labels + rowBase + wm * 32 + (r >> 1) * 16 + ((r & 1) << 3) + (lane >> 2));

    float m[4], s[4], ps[4];
    int pc[4];
    #pragma unroll
    for (int r = 0; r < 4; ++r) { m[r] = -CUDART_INF_F; s[r] = 0.f; ps[r] = 0.f; pc[r] = 0; }

    float4* red_row = reinterpret_cast<float4*>((char*)sh + RED_ROW_OFF);
    float4* red_col = reinterpret_cast<float4*>((char*)sh + RED_COL_OFF);

    float acc[2][4][4];

    #pragma unroll 1
    for (int t = 0; t < nt; ++t) {
        const int st = t & 1;
        if (t + 1 < nt) {
            issue_b(J0 + t + 1, st ^ 1);
            asm volatile("cp.async.wait_group 1;" ::: "memory");
        } else {
            asm volatile("cp.async.wait_group 0;" ::: "memory");
        }
        __syncthreads();   // stage st visible; prior readers drained

        // ---- GEMM 128x128x128 on stage st ----
        #pragma unroll
        for (int mt = 0; mt < 2; ++mt)
            #pragma unroll
            for (int ntt = 0; ntt < 4; ++ntt)
                #pragma unroll
                for (int e = 0; e < 4; ++e) acc[mt][ntt][e] = 0.f;
        #pragma unroll
        for (int kc = 0; kc < 8; ++kc) {
            uint32_t ah[2][4], bh[2][4];
            #pragma unroll
            for (int mt = 0; mt < 2; ++mt) ldsm_x4(ah[mt], aAddr[mt] + kc * 32);
            #pragma unroll
            for (int bt = 0; bt < 2; ++bt) ldsm_x4(bh[bt], bAddr[st][bt] + kc * 32);
            #pragma unroll
            for (int mt = 0; mt < 2; ++mt)
                #pragma unroll
                for (int bt = 0; bt < 2; ++bt) {
                    mma16816(acc[mt][bt * 2],     ah[mt], bh[bt][0], bh[bt][1]);
                    mma16816(acc[mt][bt * 2 + 1], ah[mt], bh[bt][2], bh[bt][3]);
                }
        }

        const int J = J0 + t;
        const int colBase = J * BLK;
        int lc[8];
        #pragma unroll
        for (int j = 0; j < 8; ++j)
            lc[j] = __ldg(labels + colBase + wn * 32 + (j >> 1) * 8 + (lane & 3) * 2 + (j & 1));

        // ---- row fold into running stats ----
        #pragma unroll
        for (int r = 0; r < 4; ++r) {
            const int growr = rowBase + wm * 32 + (r >> 1) * 16 + ((r & 1) << 3) + (lane >> 2);
            float lh[8], tmax = -CUDART_INF_F;
            #pragma unroll
            for (int j = 0; j < 8; ++j) {
                float v = acc[r >> 1][j >> 1][((r & 1) << 1) | (j & 1)];
                int gcol = colBase + wn * 32 + (j >> 1) * 8 + (lane & 3) * 2 + (j & 1);
                bool dg = (gcol == growr);              // only true when J == I
                if (!dg && lc[j] == li[r]) { ps[r] += v; pc[r] += 1; }
                float l = dg ? -CUDART_INF_F : v * SCALE_F;
                lh[j] = l;
                tmax = fmaxf(tmax, l);
            }
            float mn = fmaxf(m[r], tmax);
            float ss = s[r] * ex2(m[r] - mn);
            #pragma unroll
            for (int j = 0; j < 8; ++j) ss += ex2(lh[j] - mn);
            m[r] = mn;
            s[r] = ss;
        }

        // ---- col fold (symmetric contribution), skip diagonal tile ----
        if (J != I) {
            #pragma unroll
            for (int j = 0; j < 8; ++j) {
                float lh[4], tmax = -CUDART_INF_F, tps = 0.f; int tpc = 0;
                #pragma unroll
                for (int r = 0; r < 4; ++r) {
                    float v = acc[r >> 1][j >> 1][((r & 1) << 1) | (j & 1)];
                    if (lc[j] == li[r]) { tps += v; tpc += 1; }
                    float l = v * SCALE_F;
                    lh[r] = l;
                    tmax = fmaxf(tmax, l);
                }
                float ss = 0.f;
                #pragma unroll
                for (int r = 0; r < 4; ++r) ss += ex2(lh[r] - tmax);
                // reduce over the 8 threads (lane>>2) sharing this column
                #pragma unroll
                for (int ox = 4; ox <= 16; ox <<= 1) {
                    float mo  = __shfl_xor_sync(0xFFFFFFFFu, tmax, ox);
                    float so  = __shfl_xor_sync(0xFFFFFFFFu, ss,   ox);
                    float pso = __shfl_xor_sync(0xFFFFFFFFu, tps,  ox);
                    int   pco = __shfl_xor_sync(0xFFFFFFFFu, tpc,  ox);
                    float nm = fmaxf(tmax, mo);
                    ss = ss * ex2(tmax - nm) + so * ex2(mo - nm);
                    tmax = nm; tps += pso; tpc += pco;
                }
                if (lane < 4) {
                    const int lcol = wn * 32 + (j >> 1) * 8 + (lane & 3) * 2 + (j & 1);
                    red_col[lcol * 4 + wm] =
                        make_float4(tmax, ss, tps, __int_as_float(tpc));
                }
            }
        }

        __syncthreads();   // stage-reuse guard + red_col visibility

        if (J != I && tid < BLK) {
            float4 p0 = red_col[tid * 4 + 0], p1 = red_col[tid * 4 + 1];
            float4 p2 = red_col[tid * 4 + 2], p3 = red_col[tid * 4 + 3];
            float M = fmaxf(fmaxf(p0.x, p1.x), fmaxf(p2.x, p3.x));
            float S = p0.y * ex2(p0.x - M) + p1.y * ex2(p1.x - M) +
                      p2.y * ex2(p2.x - M) + p3.y * ex2(p3.x - M);
            float PS = p0.z + p1.z + p2.z + p3.z;
            int PC = __float_as_int(p0.w) + __float_as_int(p1.w) +
                     __float_as_int(p2.w) + __float_as_int(p3.w);
            g_partC[I][colBase + tid] = make_float4(M, S, PS, __int_as_float(PC));
        }
    }

    // ---- end of run: merge + write row partials to chunk slot ----
    #pragma unroll
    for (int r = 0; r < 4; ++r) {
        #pragma unroll
        for (int ox = 1; ox <= 2; ox <<= 1) {
            float mo  = __shfl_xor_sync(0xFFFFFFFFu, m[r],  ox);
            float so  = __shfl_xor_sync(0xFFFFFFFFu, s[r],  ox);
            float pso = __shfl_xor_sync(0xFFFFFFFFu, ps[r], ox);
            int   pco = __shfl_xor_sync(0xFFFFFFFFu, pc[r], ox);
            float nm = fmaxf(m[r], mo);
            s[r] = s[r] * ex2(m[r] - nm) + so * ex2(mo - nm);
            m[r] = nm; ps[r] += pso; pc[r] += pco;
        }
    }
    if ((lane & 3) == 0) {
        #pragma unroll
        for (int r = 0; r < 4; ++r) {
            const int lrow = wm * 32 + (r >> 1) * 16 + ((r & 1) << 3) + (lane >> 2);
            red_row[lrow * 4 + wn] =
                make_float4(m[r], s[r], ps[r], __int_as_float(pc[r]));
        }
    }
    __syncthreads();

    if (tid < BLK) {
        float4 p0 = red_row[tid * 4 + 0], p1 = red_row[tid * 4 + 1];
        float4 p2 = red_row[tid * 4 + 2], p3 = red_row[tid * 4 + 3];
        float M = fmaxf(fmaxf(p0.x, p1.x), fmaxf(p2.x, p3.x));
        float S = p0.y * ex2(p0.x - M) + p1.y * ex2(p1.x - M) +
                  p2.y * ex2(p2.x - M) + p3.y * ex2(p3.x - M);
        float PS = p0.z + p1.z + p2.z + p3.z;
        int PC = __float_as_int(p0.w) + __float_as_int(p1.w) +
                 __float_as_int(p2.w) + __float_as_int(p3.w);
        g_partR[c][rowBase + tid] = make_float4(M, S, PS, __int_as_float(PC));
    }
}

__global__ void supcon_merge_kernel() {
    int i = blockIdx.x * blockDim.x + threadIdx.x;   // BSZ threads
    const int I = i >> 7;
    float M = -CUDART_INF_F, S = 0.f, PS = 0.f; int PC = 0;
    for (int p = 0; p < I; ++p) {                    // col partials from I' < I
        float4 v = g_partC[p][i];
        float nm = fmaxf(M, v.x);
        S = S * ex2(M - nm) + v.y * ex2(v.x - nm);
        M = nm; PS += v.z; PC += __float_as_int(v.w);
    }
    const int nch = (NB - I + CHUNK - 1) >> 3;       // row-chunk partials
    for (int cc = 0; cc < nch; ++cc) {
        float4 v = g_partR[cc][i];
        float nm = fmaxf(M, v.x);
        S = S * ex2(M - nm) + v.y * ex2(v.x - nm);
        M = nm; PS += v.z; PC += __float_as_int(v.w);
    }
    double loss = 0.0; int valid = 0;
    if (PC > 0) {
        float lse = LN2_F * (M + log2f(S));   // natural-log lse
        loss = (double)(lse - PS / (TAU_F * (float)PC));
        valid = 1;
    }
    #pragma unroll
    for (int o = 16; o; o >>= 1) {
        loss  += __shfl_down_sync(0xFFFFFFFFu, loss, o);
        valid += __shfl_down_sync(0xFFFFFFFFu, valid, o);
    }
    if ((threadIdx.x & 31) == 0) {
        atomicAdd(&g_sum, loss);
        atomicAdd(&g_cnt, valid);
    }
}

__global__ void supcon_final_kernel(float* __restrict__ out) {
    int c = g_cnt; if (c < 1) c = 1;
    out[0] = (float)(g_sum / (double)c);
}

extern "C" void kernel_launch(void* const* d_in, const int* in_sizes, int n_in,
                              void* d_out, int out_size) {
    const float* z      = (const float*)d_in[0];
    const int*   labels = (const int*)d_in[1];
    float*       out    = (float*)d_out;

    static bool attr_set = false;
    if (!attr_set) {
        cudaFuncSetAttribute(supcon_main_kernel,
                             cudaFuncAttributeMaxDynamicSharedMemorySize,
                             SMEM_BYTES);
        attr_set = true;
    }

    supcon_convert_kernel<<<(BSZ * DDIM / 2) / 256, 256>>>(z);
    supcon_main_kernel<<<NRUNS, NTHR, SMEM_BYTES>>>(labels);
    supcon_merge_kernel<<<BSZ / 256, 256>>>();
    supcon_final_kernel<<<1, 1>>>(out);
}

// round 14
// speedup vs baseline: 1.2639x; 1.0748x over previous
#include <cuda_runtime.h>
#include <cuda_fp16.h>
#include <math_constants.h>
#include <stdint.h>

// SupCon multi-class loss: fused fp16 HMMA + pure-lse online softmax.
// pos_sum/n_pos moved OUT of the hot loop via class-sums:
//   pos_sum_i = z_i . C[l_i] - |z_i|^2,  n_pos_i = cnt[l_i] - 1  (exact fp32)
// Main kernel computes only the masked lse per row (fp16 GEMM, R9 pipeline).

#define TAU_F 0.1f
#define LOG2E_F 1.4426950408889634f
#define LN2_F 0.69314718055994531f
#define SCALE_F (LOG2E_F / TAU_F)

#define BSZ 8192
#define DDIM 128
#define NCLS 128                  // label slots (labels < 100)
#define BM 64
#define BN 128
#define NSPLIT 2
#define COLS_CTA (BSZ / NSPLIT)   // 4096
#define NTILES (COLS_CTA / BN)    // 32
#define NTHR 256

// SMEM in halves; row stride 136 halves (272B) -> conflict-free ldmatrix.
#define RSTR 136
#define A_HI 0
#define B_OFFH(st) ((64 * RSTR) + ((st) * (128 * RSTR)))
#define SMEM_HALVES (64 * RSTR + 2 * 128 * RSTR)
#define SMEM_BYTES (SMEM_HALVES * 2)   // 87040

__device__ __half  g_zhi[BSZ * DDIM];
__device__ float2  g_part[NSPLIT][BSZ];   // (max, sumexp) per row per col-half
__device__ float   g_C[NCLS * DDIM];      // class sums
__device__ int     g_ccnt[NCLS];          // class counts
__device__ double  g_sum;
__device__ int     g_cnt;

// ---------------- asm helpers ----------------
__device__ __forceinline__ float ex2(float x) {
    float y; asm("ex2.approx.ftz.f32 %0, %1;" : "=f"(y) : "f"(x)); return y;
}
__device__ __forceinline__ void cpa16(uint32_t sa, const void* g) {
    asm volatile("cp.async.cg.shared.global [%0], [%1], 16;" :: "r"(sa), "l"(g));
}
__device__ __forceinline__ void ldsm_x4(uint32_t* r, uint32_t addr) {
    asm volatile("ldmatrix.sync.aligned.m8n8.x4.shared.b16 {%0,%1,%2,%3}, [%4];"
                 : "=r"(r[0]), "=r"(r[1]), "=r"(r[2]), "=r"(r[3]) : "r"(addr));
}
__device__ __forceinline__ void mma16816(float* c, const uint32_t* a,
                                         uint32_t b0, uint32_t b1) {
    asm volatile(
        "mma.sync.aligned.m16n8k16.row.col.f32.f16.f16.f32 "
        "{%0,%1,%2,%3}, {%4,%5,%6,%7}, {%8,%9}, {%0,%1,%2,%3};"
        : "+f"(c[0]), "+f"(c[1]), "+f"(c[2]), "+f"(c[3])
        : "r"(a[0]), "r"(a[1]), "r"(a[2]), "r"(a[3]), "r"(b0), "r"(b1));
}

// ---------------- kernels ----------------
__global__ void supcon_zero_kernel() {
    int i = blockIdx.x * blockDim.x + threadIdx.x;
    if (i < NCLS * DDIM) g_C[i] = 0.f;
    if (i < NCLS) g_ccnt[i] = 0;
    if (i == 0) { g_sum = 0.0; g_cnt = 0; }
}

// fp32 -> fp16 convert + class-sum accumulation
__global__ void supcon_convert_kernel(const float* __restrict__ z,
                                      const int* __restrict__ labels) {
    int i = blockIdx.x * blockDim.x + threadIdx.x;   // BSZ*64 float2 elems
    int row = i >> 6, d2 = i & 63;
    float2 f = reinterpret_cast<const float2*>(z)[i];
    reinterpret_cast<__half2*>(g_zhi)[i] = __floats2half2_rn(f.x, f.y);
    int lb = labels[row];
    atomicAdd(&g_C[lb * DDIM + 2 * d2],     f.x);
    atomicAdd(&g_C[lb * DDIM + 2 * d2 + 1], f.y);
    if (d2 == 0) atomicAdd(&g_ccnt[lb], 1);
}

__global__ __launch_bounds__(NTHR, 2)
void supcon_main_kernel() {
    extern __shared__ __half sh[];
    const int tid  = threadIdx.x;
    const int lane = tid & 31;
    const int w    = tid >> 5;
    const int wm   = w & 1;          // 2 warps over M
    const int wn   = w >> 1;         // 4 warps over N
    const int cs      = blockIdx.x;             // column split 0/1
    const int rowBase = blockIdx.y * BM;
    const int colOrig = cs * COLS_CTA;
    // tile index (within this CTA) containing the diagonal, or -1
    const int tdg = (cs == (rowBase >> 12)) ? ((rowBase & 4095) >> 7) : -1;
    const uint32_t sbase = (uint32_t)__cvta_generic_to_shared(sh);

    const uint4* zhi4 = reinterpret_cast<const uint4*>(g_zhi);

    // ---- persistent A tile ----
    #pragma unroll
    for (int it = 0; it < 4; ++it) {
        int idx = tid + it * NTHR;          // 0..1023
        int row = idx >> 4, ch = idx & 15;
        uint4 v = zhi4[(rowBase + row) * 16 + ch];
        *reinterpret_cast<uint4*>(sh + A_HI + row * RSTR + ch * 8) = v;
    }

    // ---- fragment smem addresses ----
    const int arow = lane & 15, akad = (lane >> 4) * 8;
    uint32_t aAddr[2];
    #pragma unroll
    for (int mt = 0; mt < 2; ++mt)
        aAddr[mt] = sbase + (A_HI + (wm * 32 + mt * 16 + arow) * RSTR + akad) * 2;
    const int brow = ((lane >> 4) << 3) + (lane & 7);
    const int bkad = ((lane >> 3) & 1) * 8;
    uint32_t bAddr[2][2];
    #pragma unroll
    for (int st = 0; st < 2; ++st)
        #pragma unroll
        for (int bt = 0; bt < 2; ++bt)
            bAddr[st][bt] = sbase + (B_OFFH(st) +
                            (wn * 32 + bt * 16 + brow) * RSTR + bkad) * 2;

    float acc[2][4][4];
    #pragma unroll
    for (int mt = 0; mt < 2; ++mt)
        #pragma unroll
        for (int nt = 0; nt < 4; ++nt)
            #pragma unroll
            for (int e = 0; e < 4; ++e) acc[mt][nt][e] = 0.f;

    float m[4], s[4];
    #pragma unroll
    for (int r = 0; r < 4; ++r) { m[r] = -CUDART_INF_F; s[r] = 0.f; }

    auto issue_b = [&](int t, int st) {
        #pragma unroll
        for (int it = 0; it < 8; ++it) {
            int idx = tid + it * NTHR;      // 0..2047
            int row = idx >> 4, ch = idx & 15;
            cpa16(sbase + (B_OFFH(st) + row * RSTR + ch * 8) * 2,
                  zhi4 + (colOrig + t * 128 + row) * 16 + ch);
        }
        asm volatile("cp.async.commit_group;" ::: "memory");
    };

    issue_b(0, 0);

    #pragma unroll 1
    for (int t = 0; t < NTILES; ++t) {
        const int st = t & 1;
        if (t + 1 < NTILES) {
            issue_b(t + 1, st ^ 1);
            asm volatile("cp.async.wait_group 1;" ::: "memory");
        } else {
            asm volatile("cp.async.wait_group 0;" ::: "memory");
        }
        __syncthreads();

        // ---- GEMM tile t ----
        #pragma unroll
        for (int kc = 0; kc < 8; ++kc) {
            uint32_t ah[2][4], bh[2][4];
            #pragma unroll
            for (int mt = 0; mt < 2; ++mt) ldsm_x4(ah[mt], aAddr[mt] + kc * 32);
            #pragma unroll
            for (int bt = 0; bt < 2; ++bt) ldsm_x4(bh[bt], bAddr[st][bt] + kc * 32);
            #pragma unroll
            for (int mt = 0; mt < 2; ++mt)
                #pragma unroll
                for (int bt = 0; bt < 2; ++bt) {
                    mma16816(acc[mt][bt * 2],     ah[mt], bh[bt][0], bh[bt][1]);
                    mma16816(acc[mt][bt * 2 + 1], ah[mt], bh[bt][2], bh[bt][3]);
                }
        }

        // ---- pure-lse fold ----
        if (t != tdg) {
            #pragma unroll
            for (int r = 0; r < 4; ++r) {
                const int mt = r >> 1, off = (r & 1) * 2;
                float tv = -CUDART_INF_F;
                #pragma unroll
                for (int nt = 0; nt < 4; ++nt) {
                    tv = fmaxf(tv, acc[mt][nt][off]);
                    tv = fmaxf(tv, acc[mt][nt][off + 1]);
                }
                float mn = fmaxf(m[r], tv * SCALE_F);
                float ss = s[r] * ex2(m[r] - mn);
                float s0 = 0.f, s1 = 0.f;
                #pragma unroll
                for (int nt = 0; nt < 4; ++nt) {
                    s0 += ex2(fmaf(acc[mt][nt][off],     SCALE_F, -mn));
                    s1 += ex2(fmaf(acc[mt][nt][off + 1], SCALE_F, -mn));
                    acc[mt][nt][off] = 0.f;
                    acc[mt][nt][off + 1] = 0.f;
                }
                m[r] = mn; s[r] = ss + s0 + s1;
            }
        } else {
            const int colBase = colOrig + t * BN;
            #pragma unroll
            for (int r = 0; r < 4; ++r) {
                const int mt = r >> 1, off = (r & 1) * 2;
                const int growr = rowBase + wm * 32 + (r >> 1) * 16 + ((r & 1) << 3) + (lane >> 2);
                float vv[8];
                #pragma unroll
                for (int j = 0; j < 8; ++j) {
                    int gcol = colBase + wn * 32 + (j >> 1) * 8 + (lane & 3) * 2 + (j & 1);
                    float v = acc[mt][j >> 1][off + (j & 1)];
                    vv[j] = (gcol == growr) ? -CUDART_INF_F : v;
                    acc[mt][j >> 1][off + (j & 1)] = 0.f;
                }
                float tv = -CUDART_INF_F;
                #pragma unroll
                for (int j = 0; j < 8; ++j) tv = fmaxf(tv, vv[j]);
                float mn = fmaxf(m[r], tv * SCALE_F);
                float ss = s[r] * ex2(m[r] - mn);
                float s0 = 0.f, s1 = 0.f;
                #pragma unroll
                for (int j = 0; j < 8; j += 2) {
                    s0 += ex2(fmaf(vv[j],     SCALE_F, -mn));
                    s1 += ex2(fmaf(vv[j + 1], SCALE_F, -mn));
                }
                m[r] = mn; s[r] = ss + s0 + s1;
            }
        }

        __syncthreads();   // stage reuse guard
    }

    // ---- merge 4 threads (lane&3) sharing each row ----
    #pragma unroll
    for (int r = 0; r < 4; ++r) {
        #pragma unroll
        for (int ox = 1; ox <= 2; ox <<= 1) {
            float mo = __shfl_xor_sync(0xFFFFFFFFu, m[r], ox);
            float so = __shfl_xor_sync(0xFFFFFFFFu, s[r], ox);
            float nm = fmaxf(m[r], mo);
            s[r] = s[r] * ex2(m[r] - nm) + so * ex2(mo - nm);
            m[r] = nm;
        }
    }

    // ---- cross-warp merge over wn ----
    float2* red = reinterpret_cast<float2*>(sh);   // reuse A region (2KB)
    if ((lane & 3) == 0) {
        #pragma unroll
        for (int r = 0; r < 4; ++r) {
            const int lrow = wm * 32 + (r >> 1) * 16 + ((r & 1) << 3) + (lane >> 2);
            red[lrow * 4 + wn] = make_float2(m[r], s[r]);
        }
    }
    __syncthreads();

    if (tid < BM) {
        float2 p0 = red[tid * 4 + 0], p1 = red[tid * 4 + 1];
        float2 p2 = red[tid * 4 + 2], p3 = red[tid * 4 + 3];
        float M = fmaxf(fmaxf(p0.x, p1.x), fmaxf(p2.x, p3.x));
        float S = p0.y * ex2(p0.x - M) + p1.y * ex2(p1.x - M) +
                  p2.y * ex2(p2.x - M) + p3.y * ex2(p3.x - M);
        g_part[cs][rowBase + tid] = make_float2(M, S);
    }
}

// per-row: ps = z_i . C[l_i] - |z_i|^2 (exact fp32), merge col-half lse, loss
__global__ __launch_bounds__(1024, 1)
void supcon_pos_kernel(const float* __restrict__ z,
                       const int* __restrict__ labels) {
    const int lane = threadIdx.x & 31;
    const int wrp  = threadIdx.x >> 5;                // 0..31
    const int row  = blockIdx.x * 32 + wrp;
    const int l = labels[row];
    float4 zv = reinterpret_cast<const float4*>(z)[row * 32 + lane];
    float4 cv = reinterpret_cast<const float4*>(g_C + l * DDIM)[lane];
    float ps  = zv.x * cv.x + zv.y * cv.y + zv.z * cv.z + zv.w * cv.w;
    float nrm = zv.x * zv.x + zv.y * zv.y + zv.z * zv.z + zv.w * zv.w;
    #pragma unroll
    for (int o = 16; o; o >>= 1) {
        ps  += __shfl_down_sync(0xFFFFFFFFu, ps,  o);
        nrm += __shfl_down_sync(0xFFFFFFFFu, nrm, o);
    }
    __shared__ float ls[32];
    __shared__ int   lv[32];
    if (lane == 0) {
        float loss = 0.f; int valid = 0;
        float2 p0 = g_part[0][row], p1 = g_part[1][row];
        float M = fmaxf(p0.x, p1.x);
        float S = p0.y * ex2(p0.x - M) + p1.y * ex2(p1.x - M);
        int pc = g_ccnt[l] - 1;
        if (pc > 0) {
            float lse = LN2_F * (M + log2f(S));           // natural-log lse
            loss = lse - (ps - nrm) / (TAU_F * (float)pc);
            valid = 1;
        }
        ls[wrp] = loss; lv[wrp] = valid;
    }
    __syncthreads();
    if (threadIdx.x == 0) {
        double bs = 0.0; int bc = 0;
        #pragma unroll
        for (int k = 0; k < 32; ++k) { bs += (double)ls[k]; bc += lv[k]; }
        atomicAdd(&g_sum, bs);
        atomicAdd(&g_cnt, bc);
    }
}

__global__ void supcon_final_kernel(float* __restrict__ out) {
    int c = g_cnt; if (c < 1) c = 1;
    out[0] = (float)(g_sum / (double)c);
}

extern "C" void kernel_launch(void* const* d_in, const int* in_sizes, int n_in,
                              void* d_out, int out_size) {
    const float* z      = (const float*)d_in[0];
    const int*   labels = (const int*)d_in[1];
    float*       out    = (float*)d_out;

    static bool attr_set = false;
    if (!attr_set) {
        cudaFuncSetAttribute(supcon_main_kernel,
                             cudaFuncAttributeMaxDynamicSharedMemorySize,
                             SMEM_BYTES);
        attr_set = true;
    }

    supcon_zero_kernel<<<16, 1024>>>();
    supcon_convert_kernel<<<(BSZ * DDIM / 2) / 256, 256>>>(z, labels);
    supcon_main_kernel<<<dim3(NSPLIT, BSZ / BM), NTHR, SMEM_BYTES>>>();
    supcon_pos_kernel<<<BSZ / 32, 1024>>>(z, labels);
    supcon_final_kernel<<<1, 1>>>(out);
}